// round 1
// baseline (speedup 1.0000x reference)
#include <cuda_runtime.h>

// HOAF: per-group (G=32, cpg=8) polynomial feature expansion (deg 1/2/3 ->
// 8+36+120 = 164 features) followed by per-group 8x164 matvec + combined bias.
// B=16, C=256, H=W=56 (HW=3136).
//
// Strategy: fp32-pipe-bound problem. Use Blackwell packed fma.rn.f32x2:
// each thread handles 2 adjacent pixels packed in 64-bit regs. Weights are
// staged in smem pre-duplicated as (w,w) pairs so LDS.128 yields 2 packed
// weights; all weight loads are warp-broadcast (conflict-free).

typedef unsigned long long u64;

#define HW   3136
#define NW   1312   // 164 features * 8 outputs
#define TPB  224    // 224 threads * 2 px = 448 px/block; 7 blocks cover 3136

__device__ __forceinline__ u64 fma2(u64 a, u64 b, u64 c) {
    u64 d;
    asm("fma.rn.f32x2 %0, %1, %2, %3;" : "=l"(d) : "l"(a), "l"(b), "l"(c));
    return d;
}
__device__ __forceinline__ u64 mul2(u64 a, u64 b) {
    u64 d;
    asm("mul.rn.f32x2 %0, %1, %2;" : "=l"(d) : "l"(a), "l"(b));
    return d;
}

__global__ __launch_bounds__(TPB) void hoaf_kernel(
    const float* __restrict__ x,
    const float* __restrict__ w1, const float* __restrict__ b1,
    const float* __restrict__ w2, const float* __restrict__ b2,
    const float* __restrict__ w3, const float* __restrict__ b3,
    float* __restrict__ out)
{
    __shared__ alignas(16) u64 wdup[NW];   // [feature][output], each (w,w) packed
    __shared__ u64 biasdup[8];

    const int tid = threadIdx.x;
    const int g = blockIdx.y;
    const int b = blockIdx.z;

    // Stage weights for this group, duplicated into both f32x2 lanes.
    // Combined feature index f: [0,8)=deg1 (k), [8,44)=deg2 (triu pairs),
    // [44,164)=deg3 (sorted triples) -- same ordering as the reference.
    for (int idx = tid; idx < NW; idx += TPB) {
        const int f = idx >> 3;
        const int o = idx & 7;
        float v;
        if (f < 8)        v = w1[(g * 8 + o) * 8   + f];
        else if (f < 44)  v = w2[(g * 8 + o) * 36  + (f - 8)];
        else              v = w3[(g * 8 + o) * 120 + (f - 44)];
        const unsigned int u = __float_as_uint(v);
        wdup[idx] = ((u64)u << 32) | u;
    }
    if (tid < 8) {
        const float v = b1[g * 8 + tid] + b2[g * 8 + tid] + b3[g * 8 + tid];
        const unsigned int u = __float_as_uint(v);
        biasdup[tid] = ((u64)u << 32) | u;
    }
    __syncthreads();

    // This thread's 2 adjacent pixels (8-byte aligned: HW even, p even).
    const int p = blockIdx.x * (TPB * 2) + tid * 2;
    const float* xb = x   + ((size_t)b * 256 + (size_t)g * 8) * HW + p;
    float*       ob = out + ((size_t)b * 256 + (size_t)g * 8) * HW + p;

    u64 xx[8], acc[8];
#pragma unroll
    for (int k = 0; k < 8; k++) xx[k] = *(const u64*)(xb + (size_t)k * HW);
#pragma unroll
    for (int o = 0; o < 8; o++) acc[o] = biasdup[o];

    // Accumulate one feature (packed pair) into all 8 outputs.
    auto acc8 = [&](int fbase, u64 pf) {
        const ulonglong2* wp = (const ulonglong2*)(wdup + fbase * 8);
        ulonglong2 wa = wp[0], wb = wp[1], wc = wp[2], wd = wp[3];
        acc[0] = fma2(pf, wa.x, acc[0]);
        acc[1] = fma2(pf, wa.y, acc[1]);
        acc[2] = fma2(pf, wb.x, acc[2]);
        acc[3] = fma2(pf, wb.y, acc[3]);
        acc[4] = fma2(pf, wc.x, acc[4]);
        acc[5] = fma2(pf, wc.y, acc[5]);
        acc[6] = fma2(pf, wd.x, acc[6]);
        acc[7] = fma2(pf, wd.y, acc[7]);
    };

    // Degree 1
#pragma unroll
    for (int k = 0; k < 8; k++) acc8(k, xx[k]);

    // Degree 2 + 3, fused: pij reused for the degree-3 triple products.
    int f2 = 8, f3 = 44;
#pragma unroll
    for (int i = 0; i < 8; i++) {
#pragma unroll
        for (int j = i; j < 8; j++) {
            const u64 pij = mul2(xx[i], xx[j]);
            acc8(f2, pij);
            f2++;
#pragma unroll
            for (int k = j; k < 8; k++) {
                const u64 q = mul2(pij, xx[k]);
                acc8(f3, q);
                f3++;
            }
        }
    }

#pragma unroll
    for (int o = 0; o < 8; o++) *(u64*)(ob + (size_t)o * HW) = acc[o];
}

extern "C" void kernel_launch(void* const* d_in, const int* in_sizes, int n_in,
                              void* d_out, int out_size)
{
    const float* x  = (const float*)d_in[0];
    const float* w1 = (const float*)d_in[1];
    const float* b1 = (const float*)d_in[2];
    const float* w2 = (const float*)d_in[3];
    const float* b2 = (const float*)d_in[4];
    const float* w3 = (const float*)d_in[5];
    const float* b3 = (const float*)d_in[6];

    dim3 grid(7, 32, 16);   // spatial chunks, groups, batch
    dim3 block(TPB);
    hoaf_kernel<<<grid, block>>>(x, w1, b1, w2, b2, w3, b3, (float*)d_out);
}

// round 2
// speedup vs baseline: 1.1079x; 1.1079x over previous
#include <cuda_runtime.h>

// HOAF: per-group (G=32, cpg=8) polynomial expansion (deg 1/2/3 -> 164
// features) + per-group 8x164 matvec. B=16, C=256, HW=3136.
//
// R2: R1 was l1tex-bound (92.7%) from smem weight loads (1 LDS.128 per 2
// packed FMAs). Now each thread processes 4 pixels: pixel-pair q in batch b
// AND pair q in batch b+8, so each LDS.128 weight fetch feeds 4 packed FMAs.
// Predicted: L1 ~47%, fma ~90%, ~68us.

typedef unsigned long long u64;

#define HW   3136
#define NW   1312   // 164 features * 8 outputs
#define TPB  224    // 224 threads * 2px = 448 px per block-slice; grid.x=7

__device__ __forceinline__ u64 fma2(u64 a, u64 b, u64 c) {
    u64 d;
    asm("fma.rn.f32x2 %0, %1, %2, %3;" : "=l"(d) : "l"(a), "l"(b), "l"(c));
    return d;
}
__device__ __forceinline__ u64 mul2(u64 a, u64 b) {
    u64 d;
    asm("mul.rn.f32x2 %0, %1, %2;" : "=l"(d) : "l"(a), "l"(b));
    return d;
}

__global__ __launch_bounds__(TPB) void hoaf_kernel(
    const float* __restrict__ x,
    const float* __restrict__ w1, const float* __restrict__ b1,
    const float* __restrict__ w2, const float* __restrict__ b2,
    const float* __restrict__ w3, const float* __restrict__ b3,
    float* __restrict__ out)
{
    __shared__ alignas(16) u64 wdup[NW];   // [feature][output], (w,w) packed
    __shared__ u64 biasdup[8];

    const int tid = threadIdx.x;
    const int g = blockIdx.y;
    const int b = blockIdx.z;           // 0..7 -> handles batches b and b+8

    // Stage this group's weights, duplicated into both f32x2 lanes.
    // Feature index f: [0,8)=deg1, [8,44)=deg2 (triu), [44,164)=deg3 (sorted
    // triples) -- identical ordering to the reference.
    for (int idx = tid; idx < NW; idx += TPB) {
        const int f = idx >> 3;
        const int o = idx & 7;
        float v;
        if (f < 8)        v = w1[(g * 8 + o) * 8   + f];
        else if (f < 44)  v = w2[(g * 8 + o) * 36  + (f - 8)];
        else              v = w3[(g * 8 + o) * 120 + (f - 44)];
        const unsigned int u = __float_as_uint(v);
        wdup[idx] = ((u64)u << 32) | u;
    }
    if (tid < 8) {
        const float v = b1[g * 8 + tid] + b2[g * 8 + tid] + b3[g * 8 + tid];
        const unsigned int u = __float_as_uint(v);
        biasdup[tid] = ((u64)u << 32) | u;
    }
    __syncthreads();

    // Pixel pair q (pixels 2q, 2q+1) in batch b and batch b+8.
    const int p = (blockIdx.x * TPB + tid) * 2;
    const size_t base = ((size_t)b * 256 + (size_t)g * 8) * HW + p;
    const size_t boff = (size_t)8 * 256 * HW;   // batch b -> b+8
    const float* xa = x + base;
    const float* xc = x + base + boff;
    float* oa = out + base;
    float* oc = out + base + boff;

    u64 xA[8], xB[8], accA[8], accB[8];
#pragma unroll
    for (int k = 0; k < 8; k++) {
        xA[k] = *(const u64*)(xa + (size_t)k * HW);
        xB[k] = *(const u64*)(xc + (size_t)k * HW);
    }
#pragma unroll
    for (int o = 0; o < 8; o++) { accA[o] = biasdup[o]; accB[o] = accA[o]; }

    // One feature (both pixel units) into all 8 outputs: 4 LDS.128, 16 FFMA2.
    auto acc8 = [&](int fbase, u64 fA, u64 fB) {
        const ulonglong2* wp = (const ulonglong2*)(wdup + fbase * 8);
        ulonglong2 wa = wp[0], wb = wp[1], wc = wp[2], wd = wp[3];
        accA[0] = fma2(fA, wa.x, accA[0]);  accB[0] = fma2(fB, wa.x, accB[0]);
        accA[1] = fma2(fA, wa.y, accA[1]);  accB[1] = fma2(fB, wa.y, accB[1]);
        accA[2] = fma2(fA, wb.x, accA[2]);  accB[2] = fma2(fB, wb.x, accB[2]);
        accA[3] = fma2(fA, wb.y, accA[3]);  accB[3] = fma2(fB, wb.y, accB[3]);
        accA[4] = fma2(fA, wc.x, accA[4]);  accB[4] = fma2(fB, wc.x, accB[4]);
        accA[5] = fma2(fA, wc.y, accA[5]);  accB[5] = fma2(fB, wc.y, accB[5]);
        accA[6] = fma2(fA, wd.x, accA[6]);  accB[6] = fma2(fB, wd.x, accB[6]);
        accA[7] = fma2(fA, wd.y, accA[7]);  accB[7] = fma2(fB, wd.y, accB[7]);
    };

    // Degree 1
#pragma unroll
    for (int k = 0; k < 8; k++) acc8(k, xA[k], xB[k]);

    // Degree 2 + 3 fused: pij reused for triple products.
    int f2 = 8, f3 = 44;
#pragma unroll
    for (int i = 0; i < 8; i++) {
#pragma unroll
        for (int j = i; j < 8; j++) {
            const u64 pA = mul2(xA[i], xA[j]);
            const u64 pB = mul2(xB[i], xB[j]);
            acc8(f2, pA, pB);
            f2++;
#pragma unroll
            for (int k = j; k < 8; k++) {
                acc8(f3, mul2(pA, xA[k]), mul2(pB, xB[k]));
                f3++;
            }
        }
    }

#pragma unroll
    for (int o = 0; o < 8; o++) {
        *(u64*)(oa + (size_t)o * HW) = accA[o];
        *(u64*)(oc + (size_t)o * HW) = accB[o];
    }
}

extern "C" void kernel_launch(void* const* d_in, const int* in_sizes, int n_in,
                              void* d_out, int out_size)
{
    const float* x  = (const float*)d_in[0];
    const float* w1 = (const float*)d_in[1];
    const float* b1 = (const float*)d_in[2];
    const float* w2 = (const float*)d_in[3];
    const float* b2 = (const float*)d_in[4];
    const float* w3 = (const float*)d_in[5];
    const float* b3 = (const float*)d_in[6];

    dim3 grid(7, 32, 8);    // pixel-pair chunks, groups, batch-pairs
    dim3 block(TPB);
    hoaf_kernel<<<grid, block>>>(x, w1, b1, w2, b2, w3, b3, (float*)d_out);
}

// round 3
// speedup vs baseline: 1.1124x; 1.0041x over previous
#include <cuda_runtime.h>

// HOAF: per-group (G=32, cpg=8) polynomial expansion (deg 1/2/3 -> 164
// features) + per-group 8x164 matvec. B=16, C=256, HW=3136.
//
// R2: R1 was l1tex-bound (92.7%) from smem weight loads (1 LDS.128 per 2
// packed FMAs). Now each thread processes 4 pixels: pixel-pair q in batch b
// AND pair q in batch b+8, so each LDS.128 weight fetch feeds 4 packed FMAs.
// Predicted: L1 ~47%, fma ~90%, ~68us.

typedef unsigned long long u64;

#define HW   3136
#define NW   1312   // 164 features * 8 outputs
#define TPB  224    // 224 threads * 2px = 448 px per block-slice; grid.x=7

__device__ __forceinline__ u64 fma2(u64 a, u64 b, u64 c) {
    u64 d;
    asm("fma.rn.f32x2 %0, %1, %2, %3;" : "=l"(d) : "l"(a), "l"(b), "l"(c));
    return d;
}
__device__ __forceinline__ u64 mul2(u64 a, u64 b) {
    u64 d;
    asm("mul.rn.f32x2 %0, %1, %2;" : "=l"(d) : "l"(a), "l"(b));
    return d;
}

__global__ __launch_bounds__(TPB) void hoaf_kernel(
    const float* __restrict__ x,
    const float* __restrict__ w1, const float* __restrict__ b1,
    const float* __restrict__ w2, const float* __restrict__ b2,
    const float* __restrict__ w3, const float* __restrict__ b3,
    float* __restrict__ out)
{
    __shared__ alignas(16) u64 wdup[NW];   // [feature][output], (w,w) packed
    __shared__ u64 biasdup[8];

    const int tid = threadIdx.x;
    const int g = blockIdx.y;
    const int b = blockIdx.z;           // 0..7 -> handles batches b and b+8

    // Stage this group's weights, duplicated into both f32x2 lanes.
    // Feature index f: [0,8)=deg1, [8,44)=deg2 (triu), [44,164)=deg3 (sorted
    // triples) -- identical ordering to the reference.
    for (int idx = tid; idx < NW; idx += TPB) {
        const int f = idx >> 3;
        const int o = idx & 7;
        float v;
        if (f < 8)        v = w1[(g * 8 + o) * 8   + f];
        else if (f < 44)  v = w2[(g * 8 + o) * 36  + (f - 8)];
        else              v = w3[(g * 8 + o) * 120 + (f - 44)];
        const unsigned int u = __float_as_uint(v);
        wdup[idx] = ((u64)u << 32) | u;
    }
    if (tid < 8) {
        const float v = b1[g * 8 + tid] + b2[g * 8 + tid] + b3[g * 8 + tid];
        const unsigned int u = __float_as_uint(v);
        biasdup[tid] = ((u64)u << 32) | u;
    }
    __syncthreads();

    // Pixel pair q (pixels 2q, 2q+1) in batch b and batch b+8.
    const int p = (blockIdx.x * TPB + tid) * 2;
    const size_t base = ((size_t)b * 256 + (size_t)g * 8) * HW + p;
    const size_t boff = (size_t)8 * 256 * HW;   // batch b -> b+8
    const float* xa = x + base;
    const float* xc = x + base + boff;
    float* oa = out + base;
    float* oc = out + base + boff;

    u64 xA[8], xB[8], accA[8], accB[8];
#pragma unroll
    for (int k = 0; k < 8; k++) {
        xA[k] = *(const u64*)(xa + (size_t)k * HW);
        xB[k] = *(const u64*)(xc + (size_t)k * HW);
    }
#pragma unroll
    for (int o = 0; o < 8; o++) { accA[o] = biasdup[o]; accB[o] = accA[o]; }

    // One feature (both pixel units) into all 8 outputs: 4 LDS.128, 16 FFMA2.
    auto acc8 = [&](int fbase, u64 fA, u64 fB) {
        const ulonglong2* wp = (const ulonglong2*)(wdup + fbase * 8);
        ulonglong2 wa = wp[0], wb = wp[1], wc = wp[2], wd = wp[3];
        accA[0] = fma2(fA, wa.x, accA[0]);  accB[0] = fma2(fB, wa.x, accB[0]);
        accA[1] = fma2(fA, wa.y, accA[1]);  accB[1] = fma2(fB, wa.y, accB[1]);
        accA[2] = fma2(fA, wb.x, accA[2]);  accB[2] = fma2(fB, wb.x, accB[2]);
        accA[3] = fma2(fA, wb.y, accA[3]);  accB[3] = fma2(fB, wb.y, accB[3]);
        accA[4] = fma2(fA, wc.x, accA[4]);  accB[4] = fma2(fB, wc.x, accB[4]);
        accA[5] = fma2(fA, wc.y, accA[5]);  accB[5] = fma2(fB, wc.y, accB[5]);
        accA[6] = fma2(fA, wd.x, accA[6]);  accB[6] = fma2(fB, wd.x, accB[6]);
        accA[7] = fma2(fA, wd.y, accA[7]);  accB[7] = fma2(fB, wd.y, accB[7]);
    };

    // Degree 1
#pragma unroll
    for (int k = 0; k < 8; k++) acc8(k, xA[k], xB[k]);

    // Degree 2 + 3 fused: pij reused for triple products.
    int f2 = 8, f3 = 44;
#pragma unroll
    for (int i = 0; i < 8; i++) {
#pragma unroll
        for (int j = i; j < 8; j++) {
            const u64 pA = mul2(xA[i], xA[j]);
            const u64 pB = mul2(xB[i], xB[j]);
            acc8(f2, pA, pB);
            f2++;
#pragma unroll
            for (int k = j; k < 8; k++) {
                acc8(f3, mul2(pA, xA[k]), mul2(pB, xB[k]));
                f3++;
            }
        }
    }

#pragma unroll
    for (int o = 0; o < 8; o++) {
        *(u64*)(oa + (size_t)o * HW) = accA[o];
        *(u64*)(oc + (size_t)o * HW) = accB[o];
    }
}

extern "C" void kernel_launch(void* const* d_in, const int* in_sizes, int n_in,
                              void* d_out, int out_size)
{
    const float* x  = (const float*)d_in[0];
    const float* w1 = (const float*)d_in[1];
    const float* b1 = (const float*)d_in[2];
    const float* w2 = (const float*)d_in[3];
    const float* b2 = (const float*)d_in[4];
    const float* w3 = (const float*)d_in[5];
    const float* b3 = (const float*)d_in[6];

    dim3 grid(7, 32, 8);    // pixel-pair chunks, groups, batch-pairs
    dim3 block(TPB);
    hoaf_kernel<<<grid, block>>>(x, w1, b1, w2, b2, w3, b3, (float*)d_out);
}